// round 1
// baseline (speedup 1.0000x reference)
#include <cuda_runtime.h>
#include <cuda_bf16.h>

// Problem constants
#define Bz   16
#define Ss   1024
#define Ls   512
#define Dd   1024
#define Hh   8
#define DHd  128
#define WDd  256
#define BLn  (Bz*Ls)      // 8192
#define BSn  (Bz*Ss)      // 16384
#define KFn  (Dd+WDd)     // 1280

// Scratch (static device globals — allocation-free per harness rules)
__device__ float g_SEM[BLn*Dd];     // gathered encoder rows      32MB
__device__ float g_Q  [BLn*Dd];     // Q (scaled)                 32MB
__device__ float g_K  [BSn*Dd];     // K                          64MB
__device__ float g_V  [BSn*Dd];     // V                          64MB
__device__ float g_CTX[BLn*Dd];     // attention context          32MB
__device__ float g_CAT[BLn*KFn];    // [sem2 | type_emb]          40MB
__device__ float g_EMB[BLn*Dd];     // final embedding            32MB
__device__ int   g_is64;

// ---------------------------------------------------------------------------
// dtype detection: if input indices are int64, every odd 32-bit word is 0.
__global__ void detect_kernel(const void* p) {
    __shared__ int nz;
    if (threadIdx.x == 0) nz = 0;
    __syncthreads();
    const int* q = (const int*)p;
    int bad = 0;
    for (int i = threadIdx.x * 2 + 1; i < 8192; i += 2 * blockDim.x)
        if (q[i] != 0) bad = 1;
    if (bad) atomicAdd(&nz, 1);
    __syncthreads();
    if (threadIdx.x == 0) g_is64 = (nz == 0) ? 1 : 0;
}

__device__ __forceinline__ int load_idx(const void* p, int i) {
    return g_is64 ? (int)((const long long*)p)[i] : ((const int*)p)[i];
}

// ---------------------------------------------------------------------------
// gather sem_vec rows: out[m,:] = enc[b, to_sem[m], :]
__global__ void gather_sem(const float* __restrict__ enc, const void* __restrict__ to_sem,
                           float* __restrict__ out) {
    int m = blockIdx.x;
    int b = m >> 9;
    int idx = load_idx(to_sem, m);
    const float4* src = (const float4*)(enc + (size_t)(b * Ss + idx) * Dd);
    float4* dst = (float4*)(out + (size_t)m * Dd);
    dst[threadIdx.x] = src[threadIdx.x];   // 256 threads * float4 = 1024 floats
}

// fill g_CAT[:,1024:1280] = type_emb[to_sem_type[m]]
__global__ void gather_type(const float* __restrict__ temb, const void* __restrict__ tt,
                            float* __restrict__ cat) {
    int m = blockIdx.x * 4 + (threadIdx.x >> 6);
    int l = threadIdx.x & 63;
    int t = load_idx(tt, m);
    const float4* src = (const float4*)(temb + (size_t)t * WDd);
    float4* dst = (float4*)(cat + (size_t)m * KFn + Dd);
    dst[l] = src[l];
}

// ---------------------------------------------------------------------------
// SGEMM (NT): C[m,n] = alpha * (sum_k A[m,k]*W[n,k] + bias[n])
// All dims are multiples of tiles, no bounds checks needed.
#define BM 128
#define BN 128
#define BK 16

__global__ __launch_bounds__(256) void sgemm_nt(
    const float* __restrict__ A, int lda,
    const float* __restrict__ W,
    const float* __restrict__ bias,
    float* __restrict__ C, int ldc,
    int K, float alpha)
{
    __shared__ float As[2][BK][BM];
    __shared__ float Bs[2][BK][BN];
    int tid = threadIdx.x;
    int tx = tid & 15, ty = tid >> 4;
    int bm = blockIdx.y * BM;
    int bn = blockIdx.x * BN;

    // prologue: load tile 0
    #pragma unroll
    for (int t = 0; t < 2; t++) {
        int v = tid + t * 256;
        int row = v >> 2;
        int kq = (v & 3) << 2;
        float4 a  = *(const float4*)(A + (size_t)(bm + row) * lda + kq);
        float4 bb = *(const float4*)(W + (size_t)(bn + row) * K   + kq);
        As[0][kq+0][row] = a.x;  As[0][kq+1][row] = a.y;
        As[0][kq+2][row] = a.z;  As[0][kq+3][row] = a.w;
        Bs[0][kq+0][row] = bb.x; Bs[0][kq+1][row] = bb.y;
        Bs[0][kq+2][row] = bb.z; Bs[0][kq+3][row] = bb.w;
    }
    __syncthreads();

    float acc[8][8];
    #pragma unroll
    for (int i = 0; i < 8; i++)
        #pragma unroll
        for (int j = 0; j < 8; j++) acc[i][j] = 0.f;

    const int KT = K / BK;
    for (int kt = 0; kt < KT; kt++) {
        int cur = kt & 1;
        float4 a_pf[2], b_pf[2];
        bool more = (kt + 1 < KT);
        if (more) {
            int k0 = (kt + 1) * BK;
            #pragma unroll
            for (int t = 0; t < 2; t++) {
                int v = tid + t * 256;
                int row = v >> 2;
                int kq = (v & 3) << 2;
                a_pf[t] = *(const float4*)(A + (size_t)(bm + row) * lda + k0 + kq);
                b_pf[t] = *(const float4*)(W + (size_t)(bn + row) * K   + k0 + kq);
            }
        }
        #pragma unroll
        for (int kk = 0; kk < BK; kk++) {
            float ar[8], br[8];
            *(float4*)(ar)     = *(const float4*)(&As[cur][kk][ty * 8]);
            *(float4*)(ar + 4) = *(const float4*)(&As[cur][kk][ty * 8 + 4]);
            *(float4*)(br)     = *(const float4*)(&Bs[cur][kk][tx * 8]);
            *(float4*)(br + 4) = *(const float4*)(&Bs[cur][kk][tx * 8 + 4]);
            #pragma unroll
            for (int ii = 0; ii < 8; ii++)
                #pragma unroll
                for (int jj = 0; jj < 8; jj++)
                    acc[ii][jj] = fmaf(ar[ii], br[jj], acc[ii][jj]);
        }
        if (more) {
            int nxt = cur ^ 1;
            #pragma unroll
            for (int t = 0; t < 2; t++) {
                int v = tid + t * 256;
                int row = v >> 2;
                int kq = (v & 3) << 2;
                As[nxt][kq+0][row] = a_pf[t].x; As[nxt][kq+1][row] = a_pf[t].y;
                As[nxt][kq+2][row] = a_pf[t].z; As[nxt][kq+3][row] = a_pf[t].w;
                Bs[nxt][kq+0][row] = b_pf[t].x; Bs[nxt][kq+1][row] = b_pf[t].y;
                Bs[nxt][kq+2][row] = b_pf[t].z; Bs[nxt][kq+3][row] = b_pf[t].w;
            }
            __syncthreads();
        }
    }

    // epilogue: bias + alpha, vectorized stores
    int cm = ty * 8, cn = tx * 8;
    float bv[8];
    *(float4*)(bv)     = *(const float4*)(bias + bn + cn);
    *(float4*)(bv + 4) = *(const float4*)(bias + bn + cn + 4);
    #pragma unroll
    for (int ii = 0; ii < 8; ii++) {
        float4 o0, o1;
        o0.x = alpha * (acc[ii][0] + bv[0]);
        o0.y = alpha * (acc[ii][1] + bv[1]);
        o0.z = alpha * (acc[ii][2] + bv[2]);
        o0.w = alpha * (acc[ii][3] + bv[3]);
        o1.x = alpha * (acc[ii][4] + bv[4]);
        o1.y = alpha * (acc[ii][5] + bv[5]);
        o1.z = alpha * (acc[ii][6] + bv[6]);
        o1.w = alpha * (acc[ii][7] + bv[7]);
        float* cp = C + (size_t)(bm + cm + ii) * ldc + bn + cn;
        *(float4*)(cp)     = o0;
        *(float4*)(cp + 4) = o1;
    }
}

// ---------------------------------------------------------------------------
// Sparse masked attention. One block per (b,i). Average ~3 allowed keys.
__global__ __launch_bounds__(128) void attn_kernel(
    const float* __restrict__ Q, const float* __restrict__ Kb,
    const float* __restrict__ Vb,
    const void* __restrict__ to_sem, const void* __restrict__ sem_syn,
    float* __restrict__ CTX)
{
    int bl = blockIdx.x;
    int b = bl >> 9, i = bl & 511;
    int tid = threadIdx.x;

    __shared__ int   s_idx[1024];
    __shared__ float s_sc[Hh][1024];
    __shared__ int   s_total;
    __shared__ int   s_wbase[4];

    const int is64 = g_is64;
    const long long target = (long long)(i + 1);
    const long long* ss64 = (const long long*)sem_syn;
    const int*       ss32 = (const int*)sem_syn;
    const int base = b * Ss;

    if (tid == 0) s_total = 0;
    __syncthreads();

    int lane = tid & 31, w = tid >> 5;
    unsigned lt = (1u << lane) - 1u;

    // deterministic ordered compaction of {j : sem_syn[b,j] == i+1}
    for (int c = 0; c < 8; c++) {
        int j = c * 128 + tid;
        long long v = is64 ? ss64[base + j] : (long long)ss32[base + j];
        bool pred = (v == target);
        unsigned m = __ballot_sync(0xffffffffu, pred);
        if (lane == 0) s_wbase[w] = __popc(m);
        __syncthreads();
        if (tid == 0) {
            int s = s_total;
            #pragma unroll
            for (int ww = 0; ww < 4; ww++) { int t = s_wbase[ww]; s_wbase[ww] = s; s += t; }
            s_total = s;
        }
        __syncthreads();
        if (pred) s_idx[s_wbase[w] + __popc(m & lt)] = j;
        __syncthreads();
    }

    // append self position if not already allowed via sem_syn
    int jself = load_idx(to_sem, bl);
    if (tid == 0) {
        long long vs = is64 ? ss64[base + jself] : (long long)ss32[base + jself];
        if (vs != target) { s_idx[s_total] = jself; s_total = s_total + 1; }
    }
    __syncthreads();
    const int M = s_total;

    int h = tid >> 4, l16 = tid & 15;
    const float* qp = Q + (size_t)bl * Dd + h * DHd + l16 * 8;
    float qr[8];
    *(float4*)(qr)     = *(const float4*)(qp);
    *(float4*)(qr + 4) = *(const float4*)(qp + 4);

    for (int m = 0; m < M; m++) {
        int j = s_idx[m];
        const float* kp = Kb + (size_t)(base + j) * Dd + h * DHd + l16 * 8;
        float4 k0 = *(const float4*)(kp);
        float4 k1 = *(const float4*)(kp + 4);
        float p = qr[0]*k0.x + qr[1]*k0.y + qr[2]*k0.z + qr[3]*k0.w
                + qr[4]*k1.x + qr[5]*k1.y + qr[6]*k1.z + qr[7]*k1.w;
        p += __shfl_xor_sync(0xffffffffu, p, 1);
        p += __shfl_xor_sync(0xffffffffu, p, 2);
        p += __shfl_xor_sync(0xffffffffu, p, 4);
        p += __shfl_xor_sync(0xffffffffu, p, 8);
        if (l16 == 0) s_sc[h][m] = p;
    }
    __syncthreads();

    float mx = -3.0e38f;
    for (int m = 0; m < M; m++) mx = fmaxf(mx, s_sc[h][m]);
    float den = 0.f;
    for (int m = 0; m < M; m++) den += expf(s_sc[h][m] - mx);

    float acc[8];
    #pragma unroll
    for (int c = 0; c < 8; c++) acc[c] = 0.f;
    for (int m = 0; m < M; m++) {
        float p = expf(s_sc[h][m] - mx);
        int j = s_idx[m];
        const float* vp = Vb + (size_t)(base + j) * Dd + h * DHd + l16 * 8;
        float4 v0 = *(const float4*)(vp);
        float4 v1 = *(const float4*)(vp + 4);
        acc[0] += p * v0.x; acc[1] += p * v0.y; acc[2] += p * v0.z; acc[3] += p * v0.w;
        acc[4] += p * v1.x; acc[5] += p * v1.y; acc[6] += p * v1.z; acc[7] += p * v1.w;
    }
    float inv = 1.0f / den;
    float* cp = CTX + (size_t)bl * Dd + h * DHd + l16 * 8;
    float4 o0 = {acc[0]*inv, acc[1]*inv, acc[2]*inv, acc[3]*inv};
    float4 o1 = {acc[4]*inv, acc[5]*inv, acc[6]*inv, acc[7]*inv};
    *(float4*)(cp)     = o0;
    *(float4*)(cp + 4) = o1;
}

// ---------------------------------------------------------------------------
// pack outputs: [embedding (B,L,D)] then [concat(root, embedding) (B,L+1,D)]
__global__ void write_out(const float* __restrict__ emb, const float* __restrict__ root,
                          float* __restrict__ out, int out_size) {
    const int T1 = BLn * Dd;              // 8388608
    const int T2 = Bz * (Ls + 1) * Dd;    // 8404992
    int base2, n;
    if (out_size >= T1 + T2)      { base2 = T1; n = T1 + T2; }
    else if (out_size == T2)      { base2 = 0;  n = T2; }
    else                          { base2 = -1; n = T1; }
    int n4 = n >> 2;
    for (int i4 = blockIdx.x * blockDim.x + threadIdx.x; i4 < n4;
         i4 += gridDim.x * blockDim.x) {
        int e = i4 << 2;
        float4 val;
        if (base2 >= 0 && e >= base2) {
            int off = e - base2;
            int b = off / ((Ls + 1) * Dd);
            int r = off - b * ((Ls + 1) * Dd);
            int l = r >> 10;
            int dd = r & (Dd - 1);
            if (l == 0)
                val = ((const float4*)root)[dd >> 2];
            else
                val = ((const float4*)(emb + ((size_t)(b * Ls + l - 1) << 10)))[dd >> 2];
        } else {
            val = ((const float4*)emb)[i4];
        }
        ((float4*)out)[i4] = val;
    }
}

// ---------------------------------------------------------------------------
extern "C" void kernel_launch(void* const* d_in, const int* in_sizes, int n_in,
                              void* d_out, int out_size) {
    const float* enc     = (const float*)d_in[0];
    const void*  to_sem  = d_in[1];
    const void*  tt      = d_in[2];
    const void*  sem_syn = d_in[3];
    const float* wq = (const float*)d_in[4];
    const float* bq = (const float*)d_in[5];
    const float* wk = (const float*)d_in[6];
    const float* bk = (const float*)d_in[7];
    const float* wv = (const float*)d_in[8];
    const float* bv = (const float*)d_in[9];
    const float* wo = (const float*)d_in[10];
    const float* bo = (const float*)d_in[11];
    const float* type_emb = (const float*)d_in[12];
    const float* w_proj   = (const float*)d_in[13];
    const float* b_proj   = (const float*)d_in[14];
    const float* root     = (const float*)d_in[15];

    float *pSEM, *pQ, *pK, *pV, *pCTX, *pCAT, *pEMB;
    cudaGetSymbolAddress((void**)&pSEM, g_SEM);
    cudaGetSymbolAddress((void**)&pQ,   g_Q);
    cudaGetSymbolAddress((void**)&pK,   g_K);
    cudaGetSymbolAddress((void**)&pV,   g_V);
    cudaGetSymbolAddress((void**)&pCTX, g_CTX);
    cudaGetSymbolAddress((void**)&pCAT, g_CAT);
    cudaGetSymbolAddress((void**)&pEMB, g_EMB);

    const float qscale = 0.08838834764831843f;   // 1/sqrt(128)

    detect_kernel<<<1, 512>>>(to_sem);
    gather_sem<<<BLn, 256>>>(enc, to_sem, pSEM);

    // Q = (sem @ wq.T + bq) * scale
    sgemm_nt<<<dim3(Dd / BN, BLn / BM), 256>>>(pSEM, Dd, wq, bq, pQ, Dd, Dd, qscale);
    // K, V over encoder outs
    sgemm_nt<<<dim3(Dd / BN, BSn / BM), 256>>>(enc, Dd, wk, bk, pK, Dd, Dd, 1.0f);
    sgemm_nt<<<dim3(Dd / BN, BSn / BM), 256>>>(enc, Dd, wv, bv, pV, Dd, Dd, 1.0f);

    // sparse masked attention
    attn_kernel<<<BLn, 128>>>(pQ, pK, pV, to_sem, sem_syn, pCTX);

    // O-proj written directly into concat buffer (ldc = 1280)
    sgemm_nt<<<dim3(Dd / BN, BLn / BM), 256>>>(pCTX, Dd, wo, bo, pCAT, KFn, Dd, 1.0f);
    // type embedding into concat tail
    gather_type<<<BLn / 4, 256>>>(type_emb, tt, pCAT);

    // final projection, K=1280
    sgemm_nt<<<dim3(Dd / BN, BLn / BM), 256>>>(pCAT, KFn, w_proj, b_proj, pEMB, Dd, KFn, 1.0f);

    // pack both tuple outputs
    write_out<<<2048, 256>>>(pEMB, root, (float*)d_out, out_size);
}

// round 2
// speedup vs baseline: 2.3693x; 2.3693x over previous
#include <cuda_runtime.h>
#include <cuda_bf16.h>
#include <cstdint>

// Problem constants
#define Bz   16
#define Ss   1024
#define Ls   512
#define Dd   1024
#define Hh   8
#define DHd  128
#define WDd  256
#define BLn  (Bz*Ls)      // 8192
#define BSn  (Bz*Ss)      // 16384
#define KFn  (Dd+WDd)     // 1280

// Scratch (static device globals — allocation-free per harness rules)
__device__ float g_SEM[BLn*Dd];
__device__ float g_Q  [BLn*Dd];
__device__ float g_K  [BSn*Dd];
__device__ float g_V  [BSn*Dd];
__device__ float g_CTX[BLn*Dd];
__device__ float g_CAT[BLn*KFn];
__device__ float g_EMB[BLn*Dd];
__device__ int   g_is64;

// ---------------------------------------------------------------------------
__global__ void detect_kernel(const void* p) {
    __shared__ int nz;
    if (threadIdx.x == 0) nz = 0;
    __syncthreads();
    const int* q = (const int*)p;
    int bad = 0;
    for (int i = threadIdx.x * 2 + 1; i < 8192; i += 2 * blockDim.x)
        if (q[i] != 0) bad = 1;
    if (bad) atomicAdd(&nz, 1);
    __syncthreads();
    if (threadIdx.x == 0) g_is64 = (nz == 0) ? 1 : 0;
}

__device__ __forceinline__ int load_idx(const void* p, int i) {
    return g_is64 ? (int)((const long long*)p)[i] : ((const int*)p)[i];
}

// ---------------------------------------------------------------------------
__global__ void gather_sem(const float* __restrict__ enc, const void* __restrict__ to_sem,
                           float* __restrict__ out) {
    int m = blockIdx.x;
    int b = m >> 9;
    int idx = load_idx(to_sem, m);
    const float4* src = (const float4*)(enc + (size_t)(b * Ss + idx) * Dd);
    float4* dst = (float4*)(out + (size_t)m * Dd);
    dst[threadIdx.x] = src[threadIdx.x];
}

__global__ void gather_type(const float* __restrict__ temb, const void* __restrict__ tt,
                            float* __restrict__ cat) {
    int m = blockIdx.x * 4 + (threadIdx.x >> 6);
    int l = threadIdx.x & 63;
    int t = load_idx(tt, m);
    const float4* src = (const float4*)(temb + (size_t)t * WDd);
    float4* dst = (float4*)(cat + (size_t)m * KFn + Dd);
    dst[l] = src[l];
}

// ---------------------------------------------------------------------------
// TF32 tensor-core GEMM (NT): C[m,n] = alpha*(sum_k A[m,k]*W[n,k] + bias[n])
// 128x128x16 tiles, 8 warps (2x4), mma.sync m16n8k8 tf32, fp32 accumulate.
#define BM 128
#define BN 128
#define BK 16
#define BKp 20   // pad: g*20+t mod 32 is a bank permutation -> conflict-free frags

__device__ __forceinline__ uint32_t f2tf(float f) {
    uint32_t r;
    asm("cvt.rna.tf32.f32 %0, %1;" : "=r"(r) : "f"(f));
    return r;
}

__device__ __forceinline__ void mma_tf32(float c[4],
    uint32_t a0, uint32_t a1, uint32_t a2, uint32_t a3,
    uint32_t b0, uint32_t b1)
{
    asm volatile(
        "mma.sync.aligned.m16n8k8.row.col.f32.tf32.tf32.f32 "
        "{%0,%1,%2,%3}, {%4,%5,%6,%7}, {%8,%9}, {%0,%1,%2,%3};"
        : "+f"(c[0]), "+f"(c[1]), "+f"(c[2]), "+f"(c[3])
        : "r"(a0), "r"(a1), "r"(a2), "r"(a3), "r"(b0), "r"(b1));
}

__global__ __launch_bounds__(256, 1) void gemm_tf32(
    const float* __restrict__ A, int lda,
    const float* __restrict__ W,
    const float* __restrict__ bias,
    float* __restrict__ C, int ldc,
    int K, float alpha)
{
    __shared__ uint32_t As[2][BM][BKp];   // 20 KB
    __shared__ uint32_t Bs[2][BN][BKp];   // 20 KB

    const int tid  = threadIdx.x;
    const int warp = tid >> 5;
    const int lane = tid & 31;
    const int wm = warp >> 2;             // 0..1  (64-row slab)
    const int wn = warp & 3;              // 0..3  (32-col slab)
    const int g  = lane >> 2;             // 0..7
    const int t  = lane & 3;              // 0..3
    const int bm = blockIdx.y * BM;
    const int bn = blockIdx.x * BN;

    // ---- stage 0 load (convert to tf32 at store) ----
    #pragma unroll
    for (int tp = 0; tp < 2; tp++) {
        int v = tid + tp * 256;
        int row = v >> 2;
        int kq = (v & 3) << 2;
        float4 a  = *(const float4*)(A + (size_t)(bm + row) * lda + kq);
        float4 bb = *(const float4*)(W + (size_t)(bn + row) * K   + kq);
        As[0][row][kq+0] = f2tf(a.x);  As[0][row][kq+1] = f2tf(a.y);
        As[0][row][kq+2] = f2tf(a.z);  As[0][row][kq+3] = f2tf(a.w);
        Bs[0][row][kq+0] = f2tf(bb.x); Bs[0][row][kq+1] = f2tf(bb.y);
        Bs[0][row][kq+2] = f2tf(bb.z); Bs[0][row][kq+3] = f2tf(bb.w);
    }
    __syncthreads();

    float acc[4][4][4];
    #pragma unroll
    for (int i = 0; i < 4; i++)
        #pragma unroll
        for (int j = 0; j < 4; j++)
            #pragma unroll
            for (int r = 0; r < 4; r++) acc[i][j][r] = 0.f;

    const int KT = K / BK;
    for (int kt = 0; kt < KT; kt++) {
        int cur = kt & 1;
        float4 a_pf[2], b_pf[2];
        bool more = (kt + 1 < KT);
        if (more) {
            int k0 = (kt + 1) * BK;
            #pragma unroll
            for (int tp = 0; tp < 2; tp++) {
                int v = tid + tp * 256;
                int row = v >> 2;
                int kq = (v & 3) << 2;
                a_pf[tp] = *(const float4*)(A + (size_t)(bm + row) * lda + k0 + kq);
                b_pf[tp] = *(const float4*)(W + (size_t)(bn + row) * K   + k0 + kq);
            }
        }

        #pragma unroll
        for (int k8 = 0; k8 < 2; k8++) {
            const int kc = k8 * 8;
            uint32_t af[4][4], bf[4][2];
            #pragma unroll
            for (int mt = 0; mt < 4; mt++) {
                int rm = wm * 64 + mt * 16;
                af[mt][0] = As[cur][rm + g    ][kc + t];
                af[mt][1] = As[cur][rm + g + 8][kc + t];
                af[mt][2] = As[cur][rm + g    ][kc + t + 4];
                af[mt][3] = As[cur][rm + g + 8][kc + t + 4];
            }
            #pragma unroll
            for (int nt = 0; nt < 4; nt++) {
                int cn = wn * 32 + nt * 8 + g;
                bf[nt][0] = Bs[cur][cn][kc + t];
                bf[nt][1] = Bs[cur][cn][kc + t + 4];
            }
            #pragma unroll
            for (int mt = 0; mt < 4; mt++)
                #pragma unroll
                for (int nt = 0; nt < 4; nt++)
                    mma_tf32(acc[mt][nt],
                             af[mt][0], af[mt][1], af[mt][2], af[mt][3],
                             bf[nt][0], bf[nt][1]);
        }

        if (more) {
            int nxt = cur ^ 1;
            #pragma unroll
            for (int tp = 0; tp < 2; tp++) {
                int v = tid + tp * 256;
                int row = v >> 2;
                int kq = (v & 3) << 2;
                As[nxt][row][kq+0] = f2tf(a_pf[tp].x); As[nxt][row][kq+1] = f2tf(a_pf[tp].y);
                As[nxt][row][kq+2] = f2tf(a_pf[tp].z); As[nxt][row][kq+3] = f2tf(a_pf[tp].w);
                Bs[nxt][row][kq+0] = f2tf(b_pf[tp].x); Bs[nxt][row][kq+1] = f2tf(b_pf[tp].y);
                Bs[nxt][row][kq+2] = f2tf(b_pf[tp].z); Bs[nxt][row][kq+3] = f2tf(b_pf[tp].w);
            }
            __syncthreads();
        }
    }

    // ---- epilogue: bias + alpha, float2 stores ----
    #pragma unroll
    for (int nt = 0; nt < 4; nt++) {
        int c0 = bn + wn * 32 + nt * 8 + 2 * t;
        float2 bv = *(const float2*)(bias + c0);
        #pragma unroll
        for (int mt = 0; mt < 4; mt++) {
            int r0 = bm + wm * 64 + mt * 16 + g;
            float2 o0, o1;
            o0.x = alpha * (acc[mt][nt][0] + bv.x);
            o0.y = alpha * (acc[mt][nt][1] + bv.y);
            o1.x = alpha * (acc[mt][nt][2] + bv.x);
            o1.y = alpha * (acc[mt][nt][3] + bv.y);
            *(float2*)(C + (size_t)r0 * ldc + c0)       = o0;
            *(float2*)(C + (size_t)(r0 + 8) * ldc + c0) = o1;
        }
    }
}

// ---------------------------------------------------------------------------
// Sparse masked attention. One block per (b,i). Average ~3 allowed keys.
__global__ __launch_bounds__(128) void attn_kernel(
    const float* __restrict__ Q, const float* __restrict__ Kb,
    const float* __restrict__ Vb,
    const void* __restrict__ to_sem, const void* __restrict__ sem_syn,
    float* __restrict__ CTX)
{
    int bl = blockIdx.x;
    int b = bl >> 9, i = bl & 511;
    int tid = threadIdx.x;

    __shared__ int   s_idx[1024];
    __shared__ float s_sc[Hh][1024];
    __shared__ int   s_total;
    __shared__ int   s_wbase[4];

    const int is64 = g_is64;
    const long long target = (long long)(i + 1);
    const long long* ss64 = (const long long*)sem_syn;
    const int*       ss32 = (const int*)sem_syn;
    const int base = b * Ss;

    if (tid == 0) s_total = 0;
    __syncthreads();

    int lane = tid & 31, w = tid >> 5;
    unsigned lt = (1u << lane) - 1u;

    for (int c = 0; c < 8; c++) {
        int j = c * 128 + tid;
        long long v = is64 ? ss64[base + j] : (long long)ss32[base + j];
        bool pred = (v == target);
        unsigned m = __ballot_sync(0xffffffffu, pred);
        if (lane == 0) s_wbase[w] = __popc(m);
        __syncthreads();
        if (tid == 0) {
            int s = s_total;
            #pragma unroll
            for (int ww = 0; ww < 4; ww++) { int tt2 = s_wbase[ww]; s_wbase[ww] = s; s += tt2; }
            s_total = s;
        }
        __syncthreads();
        if (pred) s_idx[s_wbase[w] + __popc(m & lt)] = j;
        __syncthreads();
    }

    int jself = load_idx(to_sem, bl);
    if (tid == 0) {
        long long vs = is64 ? ss64[base + jself] : (long long)ss32[base + jself];
        if (vs != target) { s_idx[s_total] = jself; s_total = s_total + 1; }
    }
    __syncthreads();
    const int M = s_total;

    int h = tid >> 4, l16 = tid & 15;
    const float* qp = Q + (size_t)bl * Dd + h * DHd + l16 * 8;
    float qr[8];
    *(float4*)(qr)     = *(const float4*)(qp);
    *(float4*)(qr + 4) = *(const float4*)(qp + 4);

    for (int m = 0; m < M; m++) {
        int j = s_idx[m];
        const float* kp = Kb + (size_t)(base + j) * Dd + h * DHd + l16 * 8;
        float4 k0 = *(const float4*)(kp);
        float4 k1 = *(const float4*)(kp + 4);
        float p = qr[0]*k0.x + qr[1]*k0.y + qr[2]*k0.z + qr[3]*k0.w
                + qr[4]*k1.x + qr[5]*k1.y + qr[6]*k1.z + qr[7]*k1.w;
        p += __shfl_xor_sync(0xffffffffu, p, 1);
        p += __shfl_xor_sync(0xffffffffu, p, 2);
        p += __shfl_xor_sync(0xffffffffu, p, 4);
        p += __shfl_xor_sync(0xffffffffu, p, 8);
        if (l16 == 0) s_sc[h][m] = p;
    }
    __syncthreads();

    float mx = -3.0e38f;
    for (int m = 0; m < M; m++) mx = fmaxf(mx, s_sc[h][m]);
    float den = 0.f;
    for (int m = 0; m < M; m++) den += expf(s_sc[h][m] - mx);

    float acc[8];
    #pragma unroll
    for (int c = 0; c < 8; c++) acc[c] = 0.f;
    for (int m = 0; m < M; m++) {
        float p = expf(s_sc[h][m] - mx);
        int j = s_idx[m];
        const float* vp = Vb + (size_t)(base + j) * Dd + h * DHd + l16 * 8;
        float4 v0 = *(const float4*)(vp);
        float4 v1 = *(const float4*)(vp + 4);
        acc[0] += p * v0.x; acc[1] += p * v0.y; acc[2] += p * v0.z; acc[3] += p * v0.w;
        acc[4] += p * v1.x; acc[5] += p * v1.y; acc[6] += p * v1.z; acc[7] += p * v1.w;
    }
    float inv = 1.0f / den;
    float* cp = CTX + (size_t)bl * Dd + h * DHd + l16 * 8;
    float4 o0 = {acc[0]*inv, acc[1]*inv, acc[2]*inv, acc[3]*inv};
    float4 o1 = {acc[4]*inv, acc[5]*inv, acc[6]*inv, acc[7]*inv};
    *(float4*)(cp)     = o0;
    *(float4*)(cp + 4) = o1;
}

// ---------------------------------------------------------------------------
__global__ void write_out(const float* __restrict__ emb, const float* __restrict__ root,
                          float* __restrict__ out, int out_size) {
    const int T1 = BLn * Dd;
    const int T2 = Bz * (Ls + 1) * Dd;
    int base2, n;
    if (out_size >= T1 + T2)      { base2 = T1; n = T1 + T2; }
    else if (out_size == T2)      { base2 = 0;  n = T2; }
    else                          { base2 = -1; n = T1; }
    int n4 = n >> 2;
    for (int i4 = blockIdx.x * blockDim.x + threadIdx.x; i4 < n4;
         i4 += gridDim.x * blockDim.x) {
        int e = i4 << 2;
        float4 val;
        if (base2 >= 0 && e >= base2) {
            int off = e - base2;
            int b = off / ((Ls + 1) * Dd);
            int r = off - b * ((Ls + 1) * Dd);
            int l = r >> 10;
            int dd = r & (Dd - 1);
            if (l == 0)
                val = ((const float4*)root)[dd >> 2];
            else
                val = ((const float4*)(emb + ((size_t)(b * Ls + l - 1) << 10)))[dd >> 2];
        } else {
            val = ((const float4*)emb)[i4];
        }
        ((float4*)out)[i4] = val;
    }
}

// ---------------------------------------------------------------------------
extern "C" void kernel_launch(void* const* d_in, const int* in_sizes, int n_in,
                              void* d_out, int out_size) {
    const float* enc     = (const float*)d_in[0];
    const void*  to_sem  = d_in[1];
    const void*  tt      = d_in[2];
    const void*  sem_syn = d_in[3];
    const float* wq = (const float*)d_in[4];
    const float* bq = (const float*)d_in[5];
    const float* wk = (const float*)d_in[6];
    const float* bk = (const float*)d_in[7];
    const float* wv = (const float*)d_in[8];
    const float* bv = (const float*)d_in[9];
    const float* wo = (const float*)d_in[10];
    const float* bo = (const float*)d_in[11];
    const float* type_emb = (const float*)d_in[12];
    const float* w_proj   = (const float*)d_in[13];
    const float* b_proj   = (const float*)d_in[14];
    const float* root     = (const float*)d_in[15];

    float *pSEM, *pQ, *pK, *pV, *pCTX, *pCAT, *pEMB;
    cudaGetSymbolAddress((void**)&pSEM, g_SEM);
    cudaGetSymbolAddress((void**)&pQ,   g_Q);
    cudaGetSymbolAddress((void**)&pK,   g_K);
    cudaGetSymbolAddress((void**)&pV,   g_V);
    cudaGetSymbolAddress((void**)&pCTX, g_CTX);
    cudaGetSymbolAddress((void**)&pCAT, g_CAT);
    cudaGetSymbolAddress((void**)&pEMB, g_EMB);

    const float qscale = 0.08838834764831843f;   // 1/sqrt(128)

    detect_kernel<<<1, 512>>>(to_sem);
    gather_sem<<<BLn, 256>>>(enc, to_sem, pSEM);

    gemm_tf32<<<dim3(Dd / BN, BLn / BM), 256>>>(pSEM, Dd, wq, bq, pQ, Dd, Dd, qscale);
    gemm_tf32<<<dim3(Dd / BN, BSn / BM), 256>>>(enc, Dd, wk, bk, pK, Dd, Dd, 1.0f);
    gemm_tf32<<<dim3(Dd / BN, BSn / BM), 256>>>(enc, Dd, wv, bv, pV, Dd, Dd, 1.0f);

    attn_kernel<<<BLn, 128>>>(pQ, pK, pV, to_sem, sem_syn, pCTX);

    gemm_tf32<<<dim3(Dd / BN, BLn / BM), 256>>>(pCTX, Dd, wo, bo, pCAT, KFn, Dd, 1.0f);
    gather_type<<<BLn / 4, 256>>>(type_emb, tt, pCAT);

    gemm_tf32<<<dim3(Dd / BN, BLn / BM), 256>>>(pCAT, KFn, w_proj, b_proj, pEMB, Dd, KFn, 1.0f);

    write_out<<<2048, 256>>>(pEMB, root, (float*)d_out, out_size);
}

// round 4
// speedup vs baseline: 7.6070x; 3.2107x over previous
#include <cuda_runtime.h>
#include <cuda_fp16.h>
#include <cstdint>

// Problem constants
#define Bz   16
#define Ss   1024
#define Ls   512
#define Dd   1024
#define Hh   8
#define DHd  128
#define WDd  256
#define BLn  (Bz*Ls)      // 8192
#define BSn  (Bz*Ss)      // 16384
#define KFn  (Dd+WDd)     // 1280

// Scratch (static device globals — allocation-free per harness rules)
__device__ __align__(128) __half g_ENCh[BSn*Dd];
__device__ __align__(128) __half g_SEMh[BLn*Dd];
__device__ __align__(128) __half g_WQh [Dd*Dd];
__device__ __align__(128) __half g_WKh [Dd*Dd];
__device__ __align__(128) __half g_WVh [Dd*Dd];
__device__ __align__(128) __half g_WOh [Dd*Dd];
__device__ __align__(128) __half g_WPh [Dd*KFn];
__device__ __align__(128) __half g_CTXh[BLn*Dd];
__device__ __align__(128) __half g_CATh[BLn*KFn];
__device__ __align__(128) float  g_Q   [BLn*Dd];
__device__ __align__(128) float  g_K   [BSn*Dd];
__device__ __align__(128) float  g_V   [BSn*Dd];
__device__ __align__(128) float  g_EMB [BLn*Dd];
__device__ int g_is64;

// ---------------------------------------------------------------------------
__device__ __forceinline__ uint32_t smem_u32(const void* p) {
    uint32_t a;
    asm("{ .reg .u64 t; cvta.to.shared.u64 t, %1; cvt.u32.u64 %0, t; }" : "=r"(a) : "l"(p));
    return a;
}

__device__ __forceinline__ void cp16(uint32_t dst, const void* src) {
    asm volatile("cp.async.cg.shared.global [%0], [%1], 16;" :: "r"(dst), "l"(src));
}
#define CP_COMMIT() asm volatile("cp.async.commit_group;" ::: "memory")
#define CP_WAIT(n)  asm volatile("cp.async.wait_group %0;" :: "n"(n) : "memory")

#define LDSM4(r, addr) \
    asm volatile("ldmatrix.sync.aligned.m8n8.x4.shared.b16 {%0,%1,%2,%3}, [%4];" \
        : "=r"((r)[0]), "=r"((r)[1]), "=r"((r)[2]), "=r"((r)[3]) : "r"(addr))

#define MMA16816(c, a, b0, b1) \
    asm volatile("mma.sync.aligned.m16n8k16.row.col.f32.f16.f16.f32 " \
        "{%0,%1,%2,%3}, {%4,%5,%6,%7}, {%8,%9}, {%0,%1,%2,%3};" \
        : "+f"((c)[0]), "+f"((c)[1]), "+f"((c)[2]), "+f"((c)[3]) \
        : "r"((a)[0]), "r"((a)[1]), "r"((a)[2]), "r"((a)[3]), "r"(b0), "r"(b1))

// ---------------------------------------------------------------------------
__global__ void detect_kernel(const void* p) {
    __shared__ int nz;
    if (threadIdx.x == 0) nz = 0;
    __syncthreads();
    const int* q = (const int*)p;
    int bad = 0;
    for (int i = threadIdx.x * 2 + 1; i < 8192; i += 2 * blockDim.x)
        if (q[i] != 0) bad = 1;
    if (bad) atomicAdd(&nz, 1);
    __syncthreads();
    if (threadIdx.x == 0) g_is64 = (nz == 0) ? 1 : 0;
}

__device__ __forceinline__ int load_idx(const void* p, int i) {
    return g_is64 ? (int)((const long long*)p)[i] : ((const int*)p)[i];
}

// fp32 -> fp16 bulk convert (8 elems/thread)
__global__ void f2h(const float* __restrict__ src, __half* __restrict__ dst, int n8) {
    int i = blockIdx.x * blockDim.x + threadIdx.x;
    if (i < n8) {
        float4 a = ((const float4*)src)[2*i];
        float4 b = ((const float4*)src)[2*i+1];
        __half2 h[4];
        h[0] = __floats2half2_rn(a.x, a.y);
        h[1] = __floats2half2_rn(a.z, a.w);
        h[2] = __floats2half2_rn(b.x, b.y);
        h[3] = __floats2half2_rn(b.z, b.w);
        ((float4*)dst)[i] = *(float4*)h;
    }
}

__global__ void gather_sem(const float* __restrict__ enc, const void* __restrict__ to_sem,
                           __half* __restrict__ out) {
    int m = blockIdx.x;
    int b = m >> 9;
    int idx = load_idx(to_sem, m);
    float4 v = ((const float4*)(enc + (size_t)(b * Ss + idx) * Dd))[threadIdx.x];
    __half2 h0 = __floats2half2_rn(v.x, v.y);
    __half2 h1 = __floats2half2_rn(v.z, v.w);
    uint2 u = { *(uint32_t*)&h0, *(uint32_t*)&h1 };
    ((uint2*)(out + (size_t)m * Dd))[threadIdx.x] = u;
}

__global__ void gather_type(const float* __restrict__ temb, const void* __restrict__ tt,
                            __half* __restrict__ cat) {
    int m = blockIdx.x * 4 + (threadIdx.x >> 6);
    int l = threadIdx.x & 63;
    int t = load_idx(tt, m);
    float4 v = ((const float4*)(temb + (size_t)t * WDd))[l];
    __half2 h0 = __floats2half2_rn(v.x, v.y);
    __half2 h1 = __floats2half2_rn(v.z, v.w);
    uint2 u = { *(uint32_t*)&h0, *(uint32_t*)&h1 };
    ((uint2*)(cat + (size_t)m * KFn + Dd))[l] = u;
}

// ---------------------------------------------------------------------------
// fp16 GEMM (NT): C[m,n] = alpha*(sum_k A[m,k]*W[n,k] + bias[n])
// 128x128 CTA tile, 4 warps of 64x64, BK=64 halves (128B rows, SW128),
// 3-stage cp.async pipeline, ldmatrix fragments, m16n8k16 fp32-accum.
#define STG_B 32768   // per-stage bytes: A 16KB + B 16KB
#define SM_TOT (3*STG_B)

__global__ __launch_bounds__(128) void gemm_h(
    const __half* __restrict__ A, int lda,
    const __half* __restrict__ W,
    const float* __restrict__ bias,
    void* __restrict__ Cv, int ldc,
    int K, float alpha, int out_half)
{
    extern __shared__ char smem[];
    const uint32_t sb = smem_u32(smem);
    const int tid  = threadIdx.x;
    const int warp = tid >> 5, lane = tid & 31;
    const int wm = warp >> 1, wn = warp & 1;
    const int bm = blockIdx.y * 128, bn = blockIdx.x * 128;
    const int KT = K >> 6;

    const __half* Ab = A + (size_t)bm * lda;
    const __half* Wb = W + (size_t)bn * K;

    auto load = [&](int stage, int kt) {
        const __half* Ap = Ab + kt * 64;
        const __half* Wp = Wb + kt * 64;
        uint32_t sa = sb + stage * STG_B;
        uint32_t sw = sa + 16384;
        #pragma unroll
        for (int i = 0; i < 8; i++) {
            int c = tid + i * 128;
            int row = c >> 3, ch = c & 7;
            uint32_t off = (row << 7) + ((ch << 4) ^ ((row & 7) << 4));
            cp16(sa + off, Ap + (size_t)row * lda + ch * 8);
            cp16(sw + off, Wp + (size_t)row * K   + ch * 8);
        }
        CP_COMMIT();
    };

    load(0, 0);
    load(1, 1);

    float acc[4][8][4];
    #pragma unroll
    for (int i = 0; i < 4; i++)
        #pragma unroll
        for (int j = 0; j < 8; j++)
            #pragma unroll
            for (int r = 0; r < 4; r++) acc[i][j][r] = 0.f;

    // lane-constant ldmatrix address components
    const int rlA = (lane & 7) + ((lane >> 3) & 1) * 8;   // A: x4 = {r0-7,c0 | r8-15,c0 | r0-7,c16 | r8-15,c16}
    const int caA = ((lane >> 4) & 1) << 4;
    const int rlB = (lane & 7) + ((lane >> 4) & 1) * 8;   // B: x4 = {n0-7,c0 | n0-7,c16 | n8-15,c0 | n8-15,c16}
    const int caB = ((lane >> 3) & 1) << 4;

    for (int kt = 0; kt < KT; kt++) {
        if (kt + 2 < KT) { CP_WAIT(1); } else { CP_WAIT(0); }
        __syncthreads();
        if (kt + 2 < KT) load((kt + 2) % 3, kt + 2);

        uint32_t ab = sb + (kt % 3) * STG_B;
        uint32_t bb = ab + 16384;

        #pragma unroll
        for (int q = 0; q < 4; q++) {
            uint32_t a[4][4], b[4][4];
            #pragma unroll
            for (int mt = 0; mt < 4; mt++) {
                int row = wm * 64 + mt * 16 + rlA;
                uint32_t addr = ab + (row << 7) + (((q << 5) + caA) ^ ((rlA & 7) << 4));
                LDSM4(a[mt], addr);
            }
            #pragma unroll
            for (int np = 0; np < 4; np++) {
                int row = wn * 64 + np * 16 + rlB;
                uint32_t addr = bb + (row << 7) + (((q << 5) + caB) ^ ((rlB & 7) << 4));
                LDSM4(b[np], addr);
            }
            #pragma unroll
            for (int mt = 0; mt < 4; mt++)
                #pragma unroll
                for (int np = 0; np < 4; np++) {
                    MMA16816(acc[mt][2*np],     a[mt], b[np][0], b[np][1]);
                    MMA16816(acc[mt][2*np + 1], a[mt], b[np][2], b[np][3]);
                }
        }
    }

    // epilogue
    const int g = lane >> 2, t2 = (lane & 3) * 2;
    #pragma unroll
    for (int nt = 0; nt < 8; nt++) {
        int c0 = bn + wn * 64 + nt * 8 + t2;
        float2 bv = *(const float2*)(bias + c0);
        #pragma unroll
        for (int mt = 0; mt < 4; mt++) {
            int r0 = bm + wm * 64 + mt * 16 + g;
            float x0 = alpha * (acc[mt][nt][0] + bv.x);
            float y0 = alpha * (acc[mt][nt][1] + bv.y);
            float x1 = alpha * (acc[mt][nt][2] + bv.x);
            float y1 = alpha * (acc[mt][nt][3] + bv.y);
            if (out_half) {
                __half* C = (__half*)Cv;
                *(__half2*)(C + (size_t)r0 * ldc + c0)       = __floats2half2_rn(x0, y0);
                *(__half2*)(C + (size_t)(r0 + 8) * ldc + c0) = __floats2half2_rn(x1, y1);
            } else {
                float* C = (float*)Cv;
                float2 o0 = {x0, y0}, o1 = {x1, y1};
                *(float2*)(C + (size_t)r0 * ldc + c0)       = o0;
                *(float2*)(C + (size_t)(r0 + 8) * ldc + c0) = o1;
            }
        }
    }
}

// ---------------------------------------------------------------------------
// Sparse masked attention (fp32 math; half CTX output)
__global__ __launch_bounds__(128) void attn_kernel(
    const float* __restrict__ Q, const float* __restrict__ Kb,
    const float* __restrict__ Vb,
    const void* __restrict__ to_sem, const void* __restrict__ sem_syn,
    __half* __restrict__ CTX)
{
    int bl = blockIdx.x;
    int b = bl >> 9, i = bl & 511;
    int tid = threadIdx.x;

    __shared__ int   s_idx[1024];
    __shared__ float s_sc[Hh][1024];
    __shared__ int   s_total;
    __shared__ int   s_wbase[4];

    const int is64 = g_is64;
    const long long target = (long long)(i + 1);
    const long long* ss64 = (const long long*)sem_syn;
    const int*       ss32 = (const int*)sem_syn;
    const int base = b * Ss;

    if (tid == 0) s_total = 0;
    __syncthreads();

    int lane = tid & 31, w = tid >> 5;
    unsigned lt = (1u << lane) - 1u;

    for (int c = 0; c < 8; c++) {
        int j = c * 128 + tid;
        long long v = is64 ? ss64[base + j] : (long long)ss32[base + j];
        bool pred = (v == target);
        unsigned m = __ballot_sync(0xffffffffu, pred);
        if (lane == 0) s_wbase[w] = __popc(m);
        __syncthreads();
        if (tid == 0) {
            int s = s_total;
            #pragma unroll
            for (int ww = 0; ww < 4; ww++) { int tt2 = s_wbase[ww]; s_wbase[ww] = s; s += tt2; }
            s_total = s;
        }
        __syncthreads();
        if (pred) s_idx[s_wbase[w] + __popc(m & lt)] = j;
        __syncthreads();
    }

    int jself = load_idx(to_sem, bl);
    if (tid == 0) {
        long long vs = is64 ? ss64[base + jself] : (long long)ss32[base + jself];
        if (vs != target) { s_idx[s_total] = jself; s_total = s_total + 1; }
    }
    __syncthreads();
    const int M = s_total;

    int h = tid >> 4, l16 = tid & 15;
    const float* qp = Q + (size_t)bl * Dd + h * DHd + l16 * 8;
    float qr[8];
    *(float4*)(qr)     = *(const float4*)(qp);
    *(float4*)(qr + 4) = *(const float4*)(qp + 4);

    for (int m = 0; m < M; m++) {
        int j = s_idx[m];
        const float* kp = Kb + (size_t)(base + j) * Dd + h * DHd + l16 * 8;
        float4 k0 = *(const float4*)(kp);
        float4 k1 = *(const float4*)(kp + 4);
        float p = qr[0]*k0.x + qr[1]*k0.y + qr[2]*k0.z + qr[3]*k0.w
                + qr[4]*k1.x + qr[5]*k1.y + qr[6]*k1.z + qr[7]*k1.w;
        p += __shfl_xor_sync(0xffffffffu, p, 1);
        p += __shfl_xor_sync(0xffffffffu, p, 2);
        p += __shfl_xor_sync(0xffffffffu, p, 4);
        p += __shfl_xor_sync(0xffffffffu, p, 8);
        if (l16 == 0) s_sc[h][m] = p;
    }
    __syncthreads();

    float mx = -3.0e38f;
    for (int m = 0; m < M; m++) mx = fmaxf(mx, s_sc[h][m]);
    float den = 0.f;
    for (int m = 0; m < M; m++) den += expf(s_sc[h][m] - mx);

    float acc[8];
    #pragma unroll
    for (int c = 0; c < 8; c++) acc[c] = 0.f;
    for (int m = 0; m < M; m++) {
        float p = expf(s_sc[h][m] - mx);
        int j = s_idx[m];
        const float* vp = Vb + (size_t)(base + j) * Dd + h * DHd + l16 * 8;
        float4 v0 = *(const float4*)(vp);
        float4 v1 = *(const float4*)(vp + 4);
        acc[0] += p * v0.x; acc[1] += p * v0.y; acc[2] += p * v0.z; acc[3] += p * v0.w;
        acc[4] += p * v1.x; acc[5] += p * v1.y; acc[6] += p * v1.z; acc[7] += p * v1.w;
    }
    float inv = 1.0f / den;
    __half2 h0 = __floats2half2_rn(acc[0]*inv, acc[1]*inv);
    __half2 h1 = __floats2half2_rn(acc[2]*inv, acc[3]*inv);
    __half2 h2 = __floats2half2_rn(acc[4]*inv, acc[5]*inv);
    __half2 h3 = __floats2half2_rn(acc[6]*inv, acc[7]*inv);
    uint4 u = { *(uint32_t*)&h0, *(uint32_t*)&h1, *(uint32_t*)&h2, *(uint32_t*)&h3 };
    *(uint4*)(CTX + (size_t)bl * Dd + h * DHd + l16 * 8) = u;
}

// ---------------------------------------------------------------------------
__global__ void write_out(const float* __restrict__ emb, const float* __restrict__ root,
                          float* __restrict__ out, int out_size) {
    const int T1 = BLn * Dd;
    const int T2 = Bz * (Ls + 1) * Dd;
    int base2, n;
    if (out_size >= T1 + T2)      { base2 = T1; n = T1 + T2; }
    else if (out_size == T2)      { base2 = 0;  n = T2; }
    else                          { base2 = -1; n = T1; }
    int n4 = n >> 2;
    for (int i4 = blockIdx.x * blockDim.x + threadIdx.x; i4 < n4;
         i4 += gridDim.x * blockDim.x) {
        int e = i4 << 2;
        float4 val;
        if (base2 >= 0 && e >= base2) {
            int off = e - base2;
            int b = off / ((Ls + 1) * Dd);
            int r = off - b * ((Ls + 1) * Dd);
            int l = r >> 10;
            int dd = r & (Dd - 1);
            if (l == 0)
                val = ((const float4*)root)[dd >> 2];
            else
                val = ((const float4*)(emb + ((size_t)(b * Ls + l - 1) << 10)))[dd >> 2];
        } else {
            val = ((const float4*)emb)[i4];
        }
        ((float4*)out)[i4] = val;
    }
}

// ---------------------------------------------------------------------------
extern "C" void kernel_launch(void* const* d_in, const int* in_sizes, int n_in,
                              void* d_out, int out_size) {
    const float* enc     = (const float*)d_in[0];
    const void*  to_sem  = d_in[1];
    const void*  tt      = d_in[2];
    const void*  sem_syn = d_in[3];
    const float* wq = (const float*)d_in[4];
    const float* bq = (const float*)d_in[5];
    const float* wk = (const float*)d_in[6];
    const float* bk = (const float*)d_in[7];
    const float* wv = (const float*)d_in[8];
    const float* bv = (const float*)d_in[9];
    const float* wo = (const float*)d_in[10];
    const float* bo = (const float*)d_in[11];
    const float* type_emb = (const float*)d_in[12];
    const float* w_proj   = (const float*)d_in[13];
    const float* b_proj   = (const float*)d_in[14];
    const float* root     = (const float*)d_in[15];

    __half *pENCh, *pSEMh, *pWQ, *pWK, *pWV, *pWO, *pWP, *pCTXh, *pCATh;
    float  *pQ, *pK, *pV, *pEMB;
    cudaGetSymbolAddress((void**)&pENCh, g_ENCh);
    cudaGetSymbolAddress((void**)&pSEMh, g_SEMh);
    cudaGetSymbolAddress((void**)&pWQ,   g_WQh);
    cudaGetSymbolAddress((void**)&pWK,   g_WKh);
    cudaGetSymbolAddress((void**)&pWV,   g_WVh);
    cudaGetSymbolAddress((void**)&pWO,   g_WOh);
    cudaGetSymbolAddress((void**)&pWP,   g_WPh);
    cudaGetSymbolAddress((void**)&pCTXh, g_CTXh);
    cudaGetSymbolAddress((void**)&pCATh, g_CATh);
    cudaGetSymbolAddress((void**)&pQ,    g_Q);
    cudaGetSymbolAddress((void**)&pK,    g_K);
    cudaGetSymbolAddress((void**)&pV,    g_V);
    cudaGetSymbolAddress((void**)&pEMB,  g_EMB);

    cudaFuncSetAttribute(gemm_h, cudaFuncAttributeMaxDynamicSharedMemorySize, SM_TOT);

    const float qscale = 0.08838834764831843f;   // 1/sqrt(128)

    detect_kernel<<<1, 512>>>(to_sem);

    // fp32 -> fp16 conversions (the conversion IS the rounding)
    f2h<<<(BSn*Dd/8 + 255)/256, 256>>>(enc, pENCh, BSn*Dd/8);
    f2h<<<(Dd*Dd/8 + 255)/256, 256>>>(wq, pWQ, Dd*Dd/8);
    f2h<<<(Dd*Dd/8 + 255)/256, 256>>>(wk, pWK, Dd*Dd/8);
    f2h<<<(Dd*Dd/8 + 255)/256, 256>>>(wv, pWV, Dd*Dd/8);
    f2h<<<(Dd*Dd/8 + 255)/256, 256>>>(wo, pWO, Dd*Dd/8);
    f2h<<<(Dd*KFn/8 + 255)/256, 256>>>(w_proj, pWP, Dd*KFn/8);

    gather_sem<<<BLn, 256>>>(enc, to_sem, pSEMh);

    gemm_h<<<dim3(Dd/128, BLn/128), 128, SM_TOT>>>(pSEMh, Dd,  pWQ, bq, pQ, Dd, Dd, qscale, 0);
    gemm_h<<<dim3(Dd/128, BSn/128), 128, SM_TOT>>>(pENCh, Dd,  pWK, bk, pK, Dd, Dd, 1.0f,   0);
    gemm_h<<<dim3(Dd/128, BSn/128), 128, SM_TOT>>>(pENCh, Dd,  pWV, bv, pV, Dd, Dd, 1.0f,   0);

    attn_kernel<<<BLn, 128>>>(pQ, pK, pV, to_sem, sem_syn, pCTXh);

    gemm_h<<<dim3(Dd/128, BLn/128), 128, SM_TOT>>>(pCTXh, Dd,  pWO, bo, pCATh, KFn, Dd, 1.0f, 1);
    gather_type<<<BLn/4, 256>>>(type_emb, tt, pCATh);

    gemm_h<<<dim3(Dd/128, BLn/128), 128, SM_TOT>>>(pCATh, KFn, pWP, b_proj, pEMB, Dd, KFn, 1.0f, 0);

    write_out<<<2048, 256>>>(pEMB, root, (float*)d_out, out_size);
}

// round 5
// speedup vs baseline: 8.0279x; 1.0553x over previous
#include <cuda_runtime.h>
#include <cuda_fp16.h>
#include <cstdint>

// Problem constants
#define Bz   16
#define Ss   1024
#define Ls   512
#define Dd   1024
#define Hh   8
#define DHd  128
#define WDd  256
#define BLn  (Bz*Ls)      // 8192
#define BSn  (Bz*Ss)      // 16384
#define KFn  (Dd+WDd)     // 1280
#define T1c  (BLn*Dd)             // 8388608
#define T2c  (Bz*(Ls+1)*Dd)       // 8404992

// Scratch (static device globals — allocation-free per harness rules)
__device__ __align__(128) __half g_ENCh[BSn*Dd];
__device__ __align__(128) __half g_SEMh[BLn*Dd];
__device__ __align__(128) __half g_WQh [Dd*Dd];
__device__ __align__(128) __half g_WKh [Dd*Dd];
__device__ __align__(128) __half g_WVh [Dd*Dd];
__device__ __align__(128) __half g_WOh [Dd*Dd];
__device__ __align__(128) __half g_WPh [Dd*KFn];
__device__ __align__(128) __half g_CTXh[BLn*Dd];
__device__ __align__(128) __half g_CATh[BLn*KFn];
__device__ __align__(128) float  g_Q   [BLn*Dd];
__device__ __align__(128) float  g_K   [BSn*Dd];
__device__ __align__(128) float  g_V   [BSn*Dd];
__device__ __align__(128) float  g_EMB [BLn*Dd];
__device__ int g_is64;

// ---------------------------------------------------------------------------
__device__ __forceinline__ uint32_t smem_u32(const void* p) {
    uint32_t a;
    asm("{ .reg .u64 t; cvta.to.shared.u64 t, %1; cvt.u32.u64 %0, t; }" : "=r"(a) : "l"(p));
    return a;
}

__device__ __forceinline__ void cp16(uint32_t dst, const void* src) {
    asm volatile("cp.async.cg.shared.global [%0], [%1], 16;" :: "r"(dst), "l"(src));
}
#define CP_COMMIT() asm volatile("cp.async.commit_group;" ::: "memory")
#define CP_WAIT(n)  asm volatile("cp.async.wait_group %0;" :: "n"(n) : "memory")

#define LDSM4(r, addr) \
    asm volatile("ldmatrix.sync.aligned.m8n8.x4.shared.b16 {%0,%1,%2,%3}, [%4];" \
        : "=r"((r)[0]), "=r"((r)[1]), "=r"((r)[2]), "=r"((r)[3]) : "r"(addr))

#define MMA16816(c, a, b0, b1) \
    asm volatile("mma.sync.aligned.m16n8k16.row.col.f32.f16.f16.f32 " \
        "{%0,%1,%2,%3}, {%4,%5,%6,%7}, {%8,%9}, {%0,%1,%2,%3};" \
        : "+f"((c)[0]), "+f"((c)[1]), "+f"((c)[2]), "+f"((c)[3]) \
        : "r"((a)[0]), "r"((a)[1]), "r"((a)[2]), "r"((a)[3]), "r"(b0), "r"(b1))

// ---------------------------------------------------------------------------
__global__ void detect_kernel(const void* p) {
    __shared__ int nz;
    if (threadIdx.x == 0) nz = 0;
    __syncthreads();
    const int* q = (const int*)p;
    int bad = 0;
    for (int i = threadIdx.x * 2 + 1; i < 8192; i += 2 * blockDim.x)
        if (q[i] != 0) bad = 1;
    if (bad) atomicAdd(&nz, 1);
    __syncthreads();
    if (threadIdx.x == 0) g_is64 = (nz == 0) ? 1 : 0;
}

__device__ __forceinline__ int load_idx(const void* p, int i) {
    return g_is64 ? (int)((const long long*)p)[i] : ((const int*)p)[i];
}

// single-launch fp32 -> fp16 conversion of all 6 tensors (segment = blockIdx.y)
__global__ void f2h_all(const float* __restrict__ e, const float* __restrict__ q,
                        const float* __restrict__ k, const float* __restrict__ v,
                        const float* __restrict__ o, const float* __restrict__ p,
                        __half* de, __half* dq, __half* dk, __half* dv,
                        __half* dw, __half* dp) {
    const float* srcs[6] = {e, q, k, v, o, p};
    __half* dsts[6] = {de, dq, dk, dv, dw, dp};
    const int n8s[6] = {BSn*Dd/8, Dd*Dd/8, Dd*Dd/8, Dd*Dd/8, Dd*Dd/8, Dd*KFn/8};
    int seg = blockIdx.y;
    const float* src = srcs[seg];
    __half* dst = dsts[seg];
    int n8 = n8s[seg];
    for (int i = blockIdx.x * blockDim.x + threadIdx.x; i < n8;
         i += gridDim.x * blockDim.x) {
        float4 a = ((const float4*)src)[2*i];
        float4 b = ((const float4*)src)[2*i+1];
        __half2 h[4];
        h[0] = __floats2half2_rn(a.x, a.y);
        h[1] = __floats2half2_rn(a.z, a.w);
        h[2] = __floats2half2_rn(b.x, b.y);
        h[3] = __floats2half2_rn(b.z, b.w);
        ((float4*)dst)[i] = *(float4*)h;
    }
}

__global__ void gather_sem(const float* __restrict__ enc, const void* __restrict__ to_sem,
                           __half* __restrict__ out) {
    int m = blockIdx.x;
    int b = m >> 9;
    int idx = load_idx(to_sem, m);
    float4 v = ((const float4*)(enc + (size_t)(b * Ss + idx) * Dd))[threadIdx.x];
    __half2 h0 = __floats2half2_rn(v.x, v.y);
    __half2 h1 = __floats2half2_rn(v.z, v.w);
    uint2 u = { *(uint32_t*)&h0, *(uint32_t*)&h1 };
    ((uint2*)(out + (size_t)m * Dd))[threadIdx.x] = u;
}

__global__ void gather_type(const float* __restrict__ temb, const void* __restrict__ tt,
                            __half* __restrict__ cat) {
    int m = blockIdx.x * 4 + (threadIdx.x >> 6);
    int l = threadIdx.x & 63;
    int t = load_idx(tt, m);
    float4 v = ((const float4*)(temb + (size_t)t * WDd))[l];
    __half2 h0 = __floats2half2_rn(v.x, v.y);
    __half2 h1 = __floats2half2_rn(v.z, v.w);
    uint2 u = { *(uint32_t*)&h0, *(uint32_t*)&h1 };
    ((uint2*)(cat + (size_t)m * KFn + Dd))[l] = u;
}

// root rows of the concat output
__global__ void write_root(const float* __restrict__ root, float* __restrict__ out) {
    int b = blockIdx.x;
    ((float4*)(out + (size_t)T1c + (size_t)b * (Ls + 1) * Dd))[threadIdx.x] =
        ((const float4*)root)[threadIdx.x];
}

// ---------------------------------------------------------------------------
// fp16 GEMM (NT): C[m,n] = alpha*(sum_k A[m,k]*W[n,k] + bias[n])
// 128x128 CTA tile, 4 warps of 64x64, BK=64 halves (128B rows, swizzled),
// 3-stage cp.async pipeline, ldmatrix fragments, m16n8k16 fp32-accum.
// mode: 0 = fp32 C; 1 = fp16 C; 2 = dual fp32 store direct to d_out tuple.
// If nx>0, blocks with blockIdx.x>=nx use {W2,bias2,Cv2} (fused second GEMM).
#define STG_B 32768
#define SM_TOT (3*STG_B)

__global__ __launch_bounds__(128) void gemm_h(
    const __half* __restrict__ A, int lda,
    const __half* __restrict__ W,
    const float* __restrict__ bias,
    void* __restrict__ Cv, int ldc,
    int K, float alpha, int mode,
    const __half* __restrict__ W2,
    const float* __restrict__ bias2,
    void* __restrict__ Cv2, int nx)
{
    extern __shared__ char smem[];
    const uint32_t sb = smem_u32(smem);
    const int tid  = threadIdx.x;
    const int warp = tid >> 5, lane = tid & 31;
    const int wm = warp >> 1, wn = warp & 1;

    const __half* Wsel = W;
    const float*  bsel = bias;
    void*         Csel = Cv;
    int bx = blockIdx.x;
    if (nx > 0 && bx >= nx) { bx -= nx; Wsel = W2; bsel = bias2; Csel = Cv2; }
    const int bm = blockIdx.y * 128, bn = bx * 128;
    const int KT = K >> 6;

    const __half* Ab = A + (size_t)bm * lda;
    const __half* Wb = Wsel + (size_t)bn * K;

    auto load = [&](int stage, int kt) {
        const __half* Ap = Ab + kt * 64;
        const __half* Wp = Wb + kt * 64;
        uint32_t sa = sb + stage * STG_B;
        uint32_t sw = sa + 16384;
        #pragma unroll
        for (int i = 0; i < 8; i++) {
            int c = tid + i * 128;
            int row = c >> 3, ch = c & 7;
            uint32_t off = (row << 7) + ((ch << 4) ^ ((row & 7) << 4));
            cp16(sa + off, Ap + (size_t)row * lda + ch * 8);
            cp16(sw + off, Wp + (size_t)row * K   + ch * 8);
        }
        CP_COMMIT();
    };

    load(0, 0);
    load(1, 1);

    float acc[4][8][4];
    #pragma unroll
    for (int i = 0; i < 4; i++)
        #pragma unroll
        for (int j = 0; j < 8; j++)
            #pragma unroll
            for (int r = 0; r < 4; r++) acc[i][j][r] = 0.f;

    const int rlA = (lane & 7) + ((lane >> 3) & 1) * 8;
    const int caA = ((lane >> 4) & 1) << 4;
    const int rlB = (lane & 7) + ((lane >> 4) & 1) * 8;
    const int caB = ((lane >> 3) & 1) << 4;

    for (int kt = 0; kt < KT; kt++) {
        if (kt + 2 < KT) { CP_WAIT(1); } else { CP_WAIT(0); }
        __syncthreads();
        if (kt + 2 < KT) load((kt + 2) % 3, kt + 2);

        uint32_t ab = sb + (kt % 3) * STG_B;
        uint32_t bb = ab + 16384;

        #pragma unroll
        for (int q = 0; q < 4; q++) {
            uint32_t a[4][4], b[4][4];
            #pragma unroll
            for (int mt = 0; mt < 4; mt++) {
                int row = wm * 64 + mt * 16 + rlA;
                uint32_t addr = ab + (row << 7) + (((q << 5) + caA) ^ ((rlA & 7) << 4));
                LDSM4(a[mt], addr);
            }
            #pragma unroll
            for (int np = 0; np < 4; np++) {
                int row = wn * 64 + np * 16 + rlB;
                uint32_t addr = bb + (row << 7) + (((q << 5) + caB) ^ ((rlB & 7) << 4));
                LDSM4(b[np], addr);
            }
            #pragma unroll
            for (int mt = 0; mt < 4; mt++)
                #pragma unroll
                for (int np = 0; np < 4; np++) {
                    MMA16816(acc[mt][2*np],     a[mt], b[np][0], b[np][1]);
                    MMA16816(acc[mt][2*np + 1], a[mt], b[np][2], b[np][3]);
                }
        }
    }

    // epilogue
    const int g = lane >> 2, t2 = (lane & 3) * 2;
    #pragma unroll
    for (int nt = 0; nt < 8; nt++) {
        int c0 = bn + wn * 64 + nt * 8 + t2;
        float2 bv = *(const float2*)(bsel + c0);
        #pragma unroll
        for (int mt = 0; mt < 4; mt++) {
            int r0 = bm + wm * 64 + mt * 16 + g;
            float x0 = alpha * (acc[mt][nt][0] + bv.x);
            float y0 = alpha * (acc[mt][nt][1] + bv.y);
            float x1 = alpha * (acc[mt][nt][2] + bv.x);
            float y1 = alpha * (acc[mt][nt][3] + bv.y);
            if (mode == 1) {
                __half* C = (__half*)Csel;
                *(__half2*)(C + (size_t)r0 * ldc + c0)       = __floats2half2_rn(x0, y0);
                *(__half2*)(C + (size_t)(r0 + 8) * ldc + c0) = __floats2half2_rn(x1, y1);
            } else if (mode == 2) {
                // dual store: embedding block + concat block of the output tuple
                float* out = (float*)Csel;
                float2 o0 = {x0, y0}, o1 = {x1, y1};
                int b0 = r0 >> 9, l0 = r0 & 511;
                int rb = r0 + 8;
                int b1 = rb >> 9, l1 = rb & 511;
                *(float2*)(out + (size_t)r0 * Dd + c0) = o0;
                *(float2*)(out + (size_t)rb * Dd + c0) = o1;
                *(float2*)(out + T1c + ((size_t)b0 * (Ls+1) + l0 + 1) * Dd + c0) = o0;
                *(float2*)(out + T1c + ((size_t)b1 * (Ls+1) + l1 + 1) * Dd + c0) = o1;
            } else {
                float* C = (float*)Csel;
                float2 o0 = {x0, y0}, o1 = {x1, y1};
                *(float2*)(C + (size_t)r0 * ldc + c0)       = o0;
                *(float2*)(C + (size_t)(r0 + 8) * ldc + c0) = o1;
            }
        }
    }
}

// ---------------------------------------------------------------------------
// Sparse masked attention; low-sync ordered compaction (thread-contiguous).
__global__ __launch_bounds__(128) void attn_kernel(
    const float* __restrict__ Q, const float* __restrict__ Kb,
    const float* __restrict__ Vb,
    const void* __restrict__ to_sem, const void* __restrict__ sem_syn,
    __half* __restrict__ CTX)
{
    int bl = blockIdx.x;
    int b = bl >> 9, i = bl & 511;
    int tid = threadIdx.x;

    __shared__ int   s_idx[1032];
    __shared__ float s_sc[Hh][1032];
    __shared__ int   s_total;
    __shared__ int   s_wtot[4];
    __shared__ int   s_wbase[4];

    const int is64 = g_is64;
    const long long target = (long long)(i + 1);
    const long long* ss64 = (const long long*)sem_syn;
    const int*       ss32 = (const int*)sem_syn;
    const int base = b * Ss;

    int lane = tid & 31, w = tid >> 5;

    // thread t owns positions [t*8, t*8+8) -> order-preserving compaction
    int loc[8];
    int cnt = 0;
    #pragma unroll
    for (int r = 0; r < 8; r++) {
        int j = tid * 8 + r;
        long long v = is64 ? ss64[base + j] : (long long)ss32[base + j];
        if (v == target) loc[cnt++] = j;
    }
    int inc = cnt;
    #pragma unroll
    for (int off = 1; off < 32; off <<= 1) {
        int n = __shfl_up_sync(0xffffffffu, inc, off);
        if (lane >= off) inc += n;
    }
    if (lane == 31) s_wtot[w] = inc;
    __syncthreads();
    if (tid == 0) {
        int s = 0;
        #pragma unroll
        for (int ww = 0; ww < 4; ww++) { int t2 = s_wtot[ww]; s_wbase[ww] = s; s += t2; }
        s_total = s;
    }
    __syncthreads();
    int basew = s_wbase[w] + inc - cnt;
    for (int c = 0; c < cnt; c++) s_idx[basew + c] = loc[c];

    int jself = load_idx(to_sem, bl);
    __syncthreads();
    if (tid == 0) {
        long long vs = is64 ? ss64[base + jself] : (long long)ss32[base + jself];
        if (vs != target) { s_idx[s_total] = jself; s_total = s_total + 1; }
    }
    __syncthreads();
    const int M = s_total;

    int h = tid >> 4, l16 = tid & 15;
    const float* qp = Q + (size_t)bl * Dd + h * DHd + l16 * 8;
    float qr[8];
    *(float4*)(qr)     = *(const float4*)(qp);
    *(float4*)(qr + 4) = *(const float4*)(qp + 4);

    for (int m = 0; m < M; m++) {
        int j = s_idx[m];
        const float* kp = Kb + (size_t)(base + j) * Dd + h * DHd + l16 * 8;
        float4 k0 = *(const float4*)(kp);
        float4 k1 = *(const float4*)(kp + 4);
        float p = qr[0]*k0.x + qr[1]*k0.y + qr[2]*k0.z + qr[3]*k0.w
                + qr[4]*k1.x + qr[5]*k1.y + qr[6]*k1.z + qr[7]*k1.w;
        p += __shfl_xor_sync(0xffffffffu, p, 1);
        p += __shfl_xor_sync(0xffffffffu, p, 2);
        p += __shfl_xor_sync(0xffffffffu, p, 4);
        p += __shfl_xor_sync(0xffffffffu, p, 8);
        if (l16 == 0) s_sc[h][m] = p;
    }
    __syncthreads();

    float mx = -3.0e38f;
    for (int m = 0; m < M; m++) mx = fmaxf(mx, s_sc[h][m]);
    float den = 0.f;
    for (int m = 0; m < M; m++) den += expf(s_sc[h][m] - mx);

    float acc[8];
    #pragma unroll
    for (int c = 0; c < 8; c++) acc[c] = 0.f;
    for (int m = 0; m < M; m++) {
        float p = expf(s_sc[h][m] - mx);
        int j = s_idx[m];
        const float* vp = Vb + (size_t)(base + j) * Dd + h * DHd + l16 * 8;
        float4 v0 = *(const float4*)(vp);
        float4 v1 = *(const float4*)(vp + 4);
        acc[0] += p * v0.x; acc[1] += p * v0.y; acc[2] += p * v0.z; acc[3] += p * v0.w;
        acc[4] += p * v1.x; acc[5] += p * v1.y; acc[6] += p * v1.z; acc[7] += p * v1.w;
    }
    float inv = 1.0f / den;
    __half2 h0 = __floats2half2_rn(acc[0]*inv, acc[1]*inv);
    __half2 h1 = __floats2half2_rn(acc[2]*inv, acc[3]*inv);
    __half2 h2 = __floats2half2_rn(acc[4]*inv, acc[5]*inv);
    __half2 h3 = __floats2half2_rn(acc[6]*inv, acc[7]*inv);
    uint4 u = { *(uint32_t*)&h0, *(uint32_t*)&h1, *(uint32_t*)&h2, *(uint32_t*)&h3 };
    *(uint4*)(CTX + (size_t)bl * Dd + h * DHd + l16 * 8) = u;
}

// ---------------------------------------------------------------------------
// fallback output packer (only used when out_size doesn't match full tuple)
__global__ void write_out(const float* __restrict__ emb, const float* __restrict__ root,
                          float* __restrict__ out, int out_size) {
    const int T1 = T1c, T2 = T2c;
    int base2, n;
    if (out_size >= T1 + T2)      { base2 = T1; n = T1 + T2; }
    else if (out_size == T2)      { base2 = 0;  n = T2; }
    else                          { base2 = -1; n = T1; }
    int n4 = n >> 2;
    for (int i4 = blockIdx.x * blockDim.x + threadIdx.x; i4 < n4;
         i4 += gridDim.x * blockDim.x) {
        int e = i4 << 2;
        float4 val;
        if (base2 >= 0 && e >= base2) {
            int off = e - base2;
            int b = off / ((Ls + 1) * Dd);
            int r = off - b * ((Ls + 1) * Dd);
            int l = r >> 10;
            int dd = r & (Dd - 1);
            if (l == 0)
                val = ((const float4*)root)[dd >> 2];
            else
                val = ((const float4*)(emb + ((size_t)(b * Ls + l - 1) << 10)))[dd >> 2];
        } else {
            val = ((const float4*)emb)[i4];
        }
        ((float4*)out)[i4] = val;
    }
}

// ---------------------------------------------------------------------------
extern "C" void kernel_launch(void* const* d_in, const int* in_sizes, int n_in,
                              void* d_out, int out_size) {
    const float* enc     = (const float*)d_in[0];
    const void*  to_sem  = d_in[1];
    const void*  tt      = d_in[2];
    const void*  sem_syn = d_in[3];
    const float* wq = (const float*)d_in[4];
    const float* bq = (const float*)d_in[5];
    const float* wk = (const float*)d_in[6];
    const float* bk = (const float*)d_in[7];
    const float* wv = (const float*)d_in[8];
    const float* bv = (const float*)d_in[9];
    const float* wo = (const float*)d_in[10];
    const float* bo = (const float*)d_in[11];
    const float* type_emb = (const float*)d_in[12];
    const float* w_proj   = (const float*)d_in[13];
    const float* b_proj   = (const float*)d_in[14];
    const float* root     = (const float*)d_in[15];

    __half *pENCh, *pSEMh, *pWQ, *pWK, *pWV, *pWO, *pWP, *pCTXh, *pCATh;
    float  *pQ, *pK, *pV, *pEMB;
    cudaGetSymbolAddress((void**)&pENCh, g_ENCh);
    cudaGetSymbolAddress((void**)&pSEMh, g_SEMh);
    cudaGetSymbolAddress((void**)&pWQ,   g_WQh);
    cudaGetSymbolAddress((void**)&pWK,   g_WKh);
    cudaGetSymbolAddress((void**)&pWV,   g_WVh);
    cudaGetSymbolAddress((void**)&pWO,   g_WOh);
    cudaGetSymbolAddress((void**)&pWP,   g_WPh);
    cudaGetSymbolAddress((void**)&pCTXh, g_CTXh);
    cudaGetSymbolAddress((void**)&pCATh, g_CATh);
    cudaGetSymbolAddress((void**)&pQ,    g_Q);
    cudaGetSymbolAddress((void**)&pK,    g_K);
    cudaGetSymbolAddress((void**)&pV,    g_V);
    cudaGetSymbolAddress((void**)&pEMB,  g_EMB);

    cudaFuncSetAttribute(gemm_h, cudaFuncAttributeMaxDynamicSharedMemorySize, SM_TOT);

    const float qscale = 0.08838834764831843f;   // 1/sqrt(128)
    const int direct = (out_size >= T1c + T2c);

    detect_kernel<<<1, 512>>>(to_sem);

    // all fp32->fp16 conversions in one launch
    f2h_all<<<dim3(256, 6), 256>>>(enc, wq, wk, wv, wo, w_proj,
                                   pENCh, pWQ, pWK, pWV, pWO, pWP);
    gather_sem<<<BLn, 256>>>(enc, to_sem, pSEMh);

    // Q projection
    gemm_h<<<dim3(8, 64), 128, SM_TOT>>>(pSEMh, Dd, pWQ, bq, pQ, Dd, Dd, qscale, 0,
                                         nullptr, nullptr, nullptr, 0);
    // K and V projections fused into one launch (shared A)
    gemm_h<<<dim3(16, 128), 128, SM_TOT>>>(pENCh, Dd, pWK, bk, pK, Dd, Dd, 1.0f, 0,
                                           pWV, bv, pV, 8);

    attn_kernel<<<BLn, 128>>>(pQ, pK, pV, to_sem, sem_syn, pCTXh);

    // O projection -> fp16 concat buffer
    gemm_h<<<dim3(8, 64), 128, SM_TOT>>>(pCTXh, Dd, pWO, bo, pCATh, KFn, Dd, 1.0f, 1,
                                         nullptr, nullptr, nullptr, 0);
    gather_type<<<BLn/4, 256>>>(type_emb, tt, pCATh);

    if (direct) {
        // final projection writes both tuple blocks of d_out directly
        gemm_h<<<dim3(8, 64), 128, SM_TOT>>>(pCATh, KFn, pWP, b_proj, d_out, Dd, KFn, 1.0f, 2,
                                             nullptr, nullptr, nullptr, 0);
        write_root<<<Bz, 256>>>(root, (float*)d_out);
    } else {
        gemm_h<<<dim3(8, 64), 128, SM_TOT>>>(pCATh, KFn, pWP, b_proj, pEMB, Dd, KFn, 1.0f, 0,
                                             nullptr, nullptr, nullptr, 0);
        write_out<<<2048, 256>>>(pEMB, root, (float*)d_out, out_size);
    }
}